// round 8
// baseline (speedup 1.0000x reference)
#include <cuda_runtime.h>

#define KSEL 8
#define NB   16384
#define BQ   65536
#define FDIM 64
#define EPSF 1e-8f
#define INV_TEMP 200.0f   // 1 / (2*0.05*0.05)

#define TILE 1024
#define TPB  32          // one warp per block
#define QPT  2           // queries per thread
#define QPB  (TPB * QPT) // 64 queries per block

// Packed anchors: {px, py, pz, inv_w2}
__device__ float4 g_pack[NB];

__global__ void prep_kernel(const float* __restrict__ pos,
                            const float* __restrict__ w) {
    int i = blockIdx.x * blockDim.x + threadIdx.x;
    if (i < NB) {
        float wi = w[i];
        float a = 1.0f / (wi * wi + EPSF);
        g_pack[i] = make_float4(pos[3 * i + 0], pos[3 * i + 1], pos[3 * i + 2], a);
    }
}

__device__ __forceinline__ void ins8(float sq, int jj, float d[KSEL], int id[KSEL], float& worst) {
    if (sq < worst) {
        d[KSEL - 1]  = sq;
        id[KSEL - 1] = jj;
#pragma unroll
        for (int k = KSEL - 1; k > 0; --k) {
            if (d[k] < d[k - 1]) {
                float td = d[k]; d[k] = d[k - 1]; d[k - 1] = td;
                int   ti = id[k]; id[k] = id[k - 1]; id[k - 1] = ti;
            }
        }
        worst = d[KSEL - 1];
    }
}

__global__ __launch_bounds__(TPB) void knn_kernel(
    const float* __restrict__ coords,
    const float* __restrict__ features,
    float* __restrict__ out)
{
    // Anchor tile and epilogue handoff share the same shared memory.
    __shared__ union SMem {
        float4 anch[TILE];                      // 16 KB
        struct {
            int   idx[QPB][KSEL];               // 2 KB
            float w[QPB][KSEL];                 // 2 KB
        } ep;
    } sm;

    const int tid = threadIdx.x;
    const int qbase = blockIdx.x * QPB;
    const int qa = qbase + tid;          // query A
    const int qb = qa + TPB;             // query B

    const float ax = coords[3 * qa + 0];
    const float ay = coords[3 * qa + 1];
    const float az = coords[3 * qa + 2];
    const float bx = coords[3 * qb + 0];
    const float by = coords[3 * qb + 1];
    const float bz = coords[3 * qb + 2];

    float da[KSEL], db[KSEL];
    int   ia[KSEL], ib[KSEL];
#pragma unroll
    for (int k = 0; k < KSEL; ++k) {
        da[k] = 3.4e38f; ia[k] = 0;
        db[k] = 3.4e38f; ib[k] = 0;
    }

    for (int t0 = 0; t0 < NB; t0 += TILE) {
        __syncthreads();
#pragma unroll
        for (int j = tid; j < TILE; j += TPB)
            sm.anch[j] = g_pack[t0 + j];
        __syncthreads();

        float wa = da[KSEL - 1];
        float wb = db[KSEL - 1];
#pragma unroll 2
        for (int j4 = 0; j4 < TILE; j4 += 4) {
            float4 p0 = sm.anch[j4 + 0];
            float4 p1 = sm.anch[j4 + 1];
            float4 p2 = sm.anch[j4 + 2];
            float4 p3 = sm.anch[j4 + 3];

            // query A, 4 chains
            float x0 = ax - p0.x, y0 = ay - p0.y, z0 = az - p0.z;
            float x1 = ax - p1.x, y1 = ay - p1.y, z1 = az - p1.z;
            float x2 = ax - p2.x, y2 = ay - p2.y, z2 = az - p2.z;
            float x3 = ax - p3.x, y3 = ay - p3.y, z3 = az - p3.z;
            float a0 = fmaf(z0, z0, fmaf(y0, y0, x0 * x0)) * p0.w;
            float a1 = fmaf(z1, z1, fmaf(y1, y1, x1 * x1)) * p1.w;
            float a2 = fmaf(z2, z2, fmaf(y2, y2, x2 * x2)) * p2.w;
            float a3 = fmaf(z3, z3, fmaf(y3, y3, x3 * x3)) * p3.w;

            // query B, 4 chains
            float u0 = bx - p0.x, v0 = by - p0.y, s0 = bz - p0.z;
            float u1 = bx - p1.x, v1 = by - p1.y, s1 = bz - p1.z;
            float u2 = bx - p2.x, v2 = by - p2.y, s2 = bz - p2.z;
            float u3 = bx - p3.x, v3 = by - p3.y, s3 = bz - p3.z;
            float b0 = fmaf(s0, s0, fmaf(v0, v0, u0 * u0)) * p0.w;
            float b1 = fmaf(s1, s1, fmaf(v1, v1, u1 * u1)) * p1.w;
            float b2 = fmaf(s2, s2, fmaf(v2, v2, u2 * u2)) * p2.w;
            float b3 = fmaf(s3, s3, fmaf(v3, v3, u3 * u3)) * p3.w;

            float ma = fminf(fminf(a0, a1), fminf(a2, a3));
            float mb = fminf(fminf(b0, b1), fminf(b2, b3));
            if ((ma < wa) || (mb < wb)) {
                const int jb = t0 + j4;
                if (ma < wa) {
                    ins8(a0, jb + 0, da, ia, wa);
                    ins8(a1, jb + 1, da, ia, wa);
                    ins8(a2, jb + 2, da, ia, wa);
                    ins8(a3, jb + 3, da, ia, wa);
                }
                if (mb < wb) {
                    ins8(b0, jb + 0, db, ib, wb);
                    ins8(b1, jb + 1, db, ib, wb);
                    ins8(b2, jb + 2, db, ib, wb);
                    ins8(b3, jb + 3, db, ib, wb);
                }
            }
        }
    }

    // Softmax over the 8 selected (logit = -sq * INV_TEMP), max-subtracted.
    __syncthreads();   // everyone done reading anchor tile before overwrite
    {
        float m0 = da[0], wsum = 0.0f, wk[KSEL];
#pragma unroll
        for (int k = 0; k < KSEL; ++k) { wk[k] = __expf((m0 - da[k]) * INV_TEMP); wsum += wk[k]; }
        float inv = 1.0f / wsum;
#pragma unroll
        for (int k = 0; k < KSEL; ++k) {
            sm.ep.w[tid][k]   = wk[k] * inv;
            sm.ep.idx[tid][k] = ia[k];
        }
    }
    {
        float m0 = db[0], wsum = 0.0f, wk[KSEL];
#pragma unroll
        for (int k = 0; k < KSEL; ++k) { wk[k] = __expf((m0 - db[k]) * INV_TEMP); wsum += wk[k]; }
        float inv = 1.0f / wsum;
#pragma unroll
        for (int k = 0; k < KSEL; ++k) {
            sm.ep.w[tid + TPB][k]   = wk[k] * inv;
            sm.ep.idx[tid + TPB][k] = ib[k];
        }
    }
    __syncthreads();

    // Cooperative gather: the warp produces the 64-float rows of its 64
    // queries; lane L accumulates features [2L, 2L+1] (float2, coalesced).
    const int lane = tid;   // TPB == 32
    for (int qq = 0; qq < QPB; ++qq) {
        float2 acc = make_float2(0.0f, 0.0f);
#pragma unroll
        for (int k = 0; k < KSEL; ++k) {
            const int   ii = sm.ep.idx[qq][k];
            const float ww = sm.ep.w[qq][k];
            float2 f = ((const float2*)(features + (size_t)ii * FDIM))[lane];
            acc.x = fmaf(ww, f.x, acc.x);
            acc.y = fmaf(ww, f.y, acc.y);
        }
        const int gq = qbase + qq;
        ((float2*)out)[gq * 32 + lane] = acc;
    }
}

extern "C" void kernel_launch(void* const* d_in, const int* in_sizes, int n_in,
                              void* d_out, int out_size) {
    const float* coords    = (const float*)d_in[0];
    const float* positions = (const float*)d_in[1];
    const float* weights   = (const float*)d_in[2];
    const float* features  = (const float*)d_in[3];
    float* out = (float*)d_out;

    prep_kernel<<<NB / 256, 256>>>(positions, weights);
    knn_kernel<<<BQ / QPB, TPB>>>(coords, features, out);
}

// round 9
// speedup vs baseline: 1.2364x; 1.2364x over previous
#include <cuda_runtime.h>

#define KSEL 8
#define NB   16384
#define BQ   65536
#define FDIM 64
#define EPSF 1e-8f
#define INV_TEMP 200.0f   // 1 / (2*0.05*0.05)

#define TILE 1024
#define HALF (TILE / 2)
#define TPB  128
#define QPB  64          // queries per block (each query -> 2 threads)

// Packed anchors: {px, py, pz, inv_w2}
__device__ float4 g_pack[NB];

__global__ void prep_kernel(const float* __restrict__ pos,
                            const float* __restrict__ w) {
    int i = blockIdx.x * blockDim.x + threadIdx.x;
    if (i < NB) {
        float wi = w[i];
        float a = 1.0f / (wi * wi + EPSF);
        g_pack[i] = make_float4(pos[3 * i + 0], pos[3 * i + 1], pos[3 * i + 2], a);
    }
}

__device__ __forceinline__ void ins8(float sq, int jj, float d[KSEL], int id[KSEL], float& worst) {
    if (sq < worst) {
        d[KSEL - 1]  = sq;
        id[KSEL - 1] = jj;
#pragma unroll
        for (int k = KSEL - 1; k > 0; --k) {
            if (d[k] < d[k - 1]) {
                float td = d[k]; d[k] = d[k - 1]; d[k - 1] = td;
                int   ti = id[k]; id[k] = id[k - 1]; id[k - 1] = ti;
            }
        }
        worst = d[KSEL - 1];
    }
}

__global__ __launch_bounds__(TPB, 7) void knn_kernel(
    const float* __restrict__ coords,
    const float* __restrict__ features,
    float* __restrict__ out)
{
    // Anchor tile, then (merge handoff + epilogue handoff) share shared memory.
    __shared__ union SMem {
        float4 anch[TILE];                      // 16 KB
        struct {
            float md[QPB][KSEL];                // 2 KB  (upper half's top-8)
            int   mi[QPB][KSEL];                // 2 KB
            float w[QPB][KSEL];                 // 2 KB  (final softmax weights)
            int   idx[QPB][KSEL];               // 2 KB
        } ep;
    } sm;

    const int tid   = threadIdx.x;
    const int qt    = tid & (QPB - 1);          // query slot 0..63
    const int sub   = tid >> 6;                 // 0 = front half, 1 = back half
    const int qbase = blockIdx.x * QPB;
    const int q     = qbase + qt;

    const float cx = coords[3 * q + 0];
    const float cy = coords[3 * q + 1];
    const float cz = coords[3 * q + 2];

    float d[KSEL];
    int   id[KSEL];
#pragma unroll
    for (int k = 0; k < KSEL; ++k) { d[k] = 3.4e38f; id[k] = 0; }

    const int jlo = sub * HALF;                 // this thread's half of each tile

    for (int t0 = 0; t0 < NB; t0 += TILE) {
        __syncthreads();
#pragma unroll
        for (int j = tid; j < TILE; j += TPB)
            sm.anch[j] = g_pack[t0 + j];
        __syncthreads();

        float worst = d[KSEL - 1];
#pragma unroll 2
        for (int j4 = jlo; j4 < jlo + HALF; j4 += 4) {
            float4 p0 = sm.anch[j4 + 0];
            float4 p1 = sm.anch[j4 + 1];
            float4 p2 = sm.anch[j4 + 2];
            float4 p3 = sm.anch[j4 + 3];

            float x0 = cx - p0.x, y0 = cy - p0.y, z0 = cz - p0.z;
            float x1 = cx - p1.x, y1 = cy - p1.y, z1 = cz - p1.z;
            float x2 = cx - p2.x, y2 = cy - p2.y, z2 = cz - p2.z;
            float x3 = cx - p3.x, y3 = cy - p3.y, z3 = cz - p3.z;

            float s0 = fmaf(z0, z0, fmaf(y0, y0, x0 * x0)) * p0.w;
            float s1 = fmaf(z1, z1, fmaf(y1, y1, x1 * x1)) * p1.w;
            float s2 = fmaf(z2, z2, fmaf(y2, y2, x2 * x2)) * p2.w;
            float s3 = fmaf(z3, z3, fmaf(y3, y3, x3 * x3)) * p3.w;

            float m = fminf(fminf(s0, s1), fminf(s2, s3));
            if (m < worst) {
                const int jb = t0 + j4;
                ins8(s0, jb + 0, d, id, worst);
                ins8(s1, jb + 1, d, id, worst);
                ins8(s2, jb + 2, d, id, worst);
                ins8(s3, jb + 3, d, id, worst);
            }
        }
    }

    __syncthreads();   // everyone done reading anchor tile before overwrite

    // Upper-half threads publish their top-8; lower-half threads merge.
    if (sub == 1) {
#pragma unroll
        for (int k = 0; k < KSEL; ++k) {
            sm.ep.md[qt][k] = d[k];
            sm.ep.mi[qt][k] = id[k];
        }
    }
    __syncthreads();

    if (sub == 0) {
        float worst = d[KSEL - 1];
#pragma unroll
        for (int k = 0; k < KSEL; ++k)
            ins8(sm.ep.md[qt][k], sm.ep.mi[qt][k], d, id, worst);

        // Softmax over the 8 selected (logit = -sq * INV_TEMP), max-subtracted.
        float m0 = d[0], wsum = 0.0f, wk[KSEL];
#pragma unroll
        for (int k = 0; k < KSEL; ++k) { wk[k] = __expf((m0 - d[k]) * INV_TEMP); wsum += wk[k]; }
        float inv = 1.0f / wsum;
#pragma unroll
        for (int k = 0; k < KSEL; ++k) {
            sm.ep.w[qt][k]   = wk[k] * inv;
            sm.ep.idx[qt][k] = id[k];
        }
    }
    __syncthreads();

    // Cooperative gather: 4 warps x 16 queries each; lane L accumulates
    // features [2L, 2L+1] (float2, coalesced 256B rows from L2).
    const int lane = tid & 31;
    const int warp = tid >> 5;
    for (int qq = 0; qq < QPB / 4; ++qq) {
        const int tq = warp * (QPB / 4) + qq;
        float2 acc = make_float2(0.0f, 0.0f);
#pragma unroll
        for (int k = 0; k < KSEL; ++k) {
            const int   ii = sm.ep.idx[tq][k];
            const float ww = sm.ep.w[tq][k];
            float2 f = ((const float2*)(features + (size_t)ii * FDIM))[lane];
            acc.x = fmaf(ww, f.x, acc.x);
            acc.y = fmaf(ww, f.y, acc.y);
        }
        const int gq = qbase + tq;
        ((float2*)out)[gq * 32 + lane] = acc;
    }
}

extern "C" void kernel_launch(void* const* d_in, const int* in_sizes, int n_in,
                              void* d_out, int out_size) {
    const float* coords    = (const float*)d_in[0];
    const float* positions = (const float*)d_in[1];
    const float* weights   = (const float*)d_in[2];
    const float* features  = (const float*)d_in[3];
    float* out = (float*)d_out;

    prep_kernel<<<NB / 256, 256>>>(positions, weights);
    knn_kernel<<<BQ / QPB, TPB>>>(coords, features, out);
}